// round 1
// baseline (speedup 1.0000x reference)
#include <cuda_runtime.h>
#include <math.h>
#include <stdint.h>

// Problem dims (fixed by the dataset)
#define N_TOK 8192      // B*L
#define DD_IN 1152
#define DD_H1 4608      // 4*D_IN
#define DD_E  256
#define NCB   4         // codebooks
#define NKC   2048      // codes per codebook
#define DPC   64        // dims per codebook
#define DD_H3 16384     // 4*H
#define DD_O  4096      // H

// ---------------- scratch (static device globals; no allocation) ----------------
__device__ float g_h1[(size_t)N_TOK * DD_H1];
__device__ float g_z [(size_t)N_TOK * DD_E];
__device__ float g_zq[(size_t)N_TOK * DD_E];
__device__ float g_h3[(size_t)N_TOK * DD_H3];
__device__ int   g_counts[NCB * NKC];
__device__ float g_commit_sum;

__device__ __forceinline__ float gelu_exact(float x) {
    // jax.nn.gelu(approximate=False) = 0.5*x*(1+erf(x/sqrt(2)))
    return 0.5f * x * (1.0f + erff(x * 0.70710678118654752440f));
}

// ---------------- init: zero accumulators (runs every graph replay) -------------
__global__ void init_kernel() {
    int i = blockIdx.x * blockDim.x + threadIdx.x;
    if (i < NCB * NKC) g_counts[i] = 0;
    if (i == 0) g_commit_sum = 0.0f;
}

// ---------------- fp32 SGEMM, C = A[MxK] * B[KxN] + bias, optional GELU ---------
// Requires: M%128==0, N%128==0, K%16==0 (all shapes here satisfy this).
template<bool GELU>
__global__ void __launch_bounds__(256) sgemm_kernel(
    int M, int N, int K,
    const float* __restrict__ A, const float* __restrict__ B,
    const float* __restrict__ bias, float* __restrict__ C)
{
    constexpr int BM = 128, BN = 128, BK = 16, TM = 8, TN = 8;
    __shared__ __align__(16) float As[BK][BM];
    __shared__ __align__(16) float Bs[BK][BN];

    const int tid = threadIdx.x;
    const int tr  = tid / (BN / TN);   // 0..15
    const int tc  = tid % (BN / TN);   // 0..15

    const float* Ablk = A + (size_t)blockIdx.y * BM * K;
    const float* Bblk = B + (size_t)blockIdx.x * BN;
    float*       Cblk = C + (size_t)blockIdx.y * BM * N + (size_t)blockIdx.x * BN;

    // A tile loads: 128 rows x 16 k, float4 along k
    const int a_row = tid >> 2;          // 0..63 (+64)
    const int a_k4  = (tid & 3) * 4;     // 0,4,8,12
    // B tile loads: 16 k x 128 n, float4 along n
    const int b_k   = tid >> 5;          // 0..7 (+8)
    const int b_n4  = (tid & 31) * 4;    // 0..124

    float acc[TM][TN] = {};
    float regM[TM], regN[TN];

    for (int k0 = 0; k0 < K; k0 += BK) {
        #pragma unroll
        for (int i = 0; i < 2; i++) {
            int row = a_row + i * 64;
            float4 v = *reinterpret_cast<const float4*>(&Ablk[(size_t)row * K + k0 + a_k4]);
            As[a_k4 + 0][row] = v.x;
            As[a_k4 + 1][row] = v.y;
            As[a_k4 + 2][row] = v.z;
            As[a_k4 + 3][row] = v.w;
        }
        #pragma unroll
        for (int i = 0; i < 2; i++) {
            int kk = b_k + i * 8;
            *reinterpret_cast<float4*>(&Bs[kk][b_n4]) =
                *reinterpret_cast<const float4*>(&Bblk[(size_t)(k0 + kk) * N + b_n4]);
        }
        __syncthreads();

        #pragma unroll
        for (int kk = 0; kk < BK; kk++) {
            *reinterpret_cast<float4*>(&regM[0]) = *reinterpret_cast<const float4*>(&As[kk][tr * TM]);
            *reinterpret_cast<float4*>(&regM[4]) = *reinterpret_cast<const float4*>(&As[kk][tr * TM + 4]);
            *reinterpret_cast<float4*>(&regN[0]) = *reinterpret_cast<const float4*>(&Bs[kk][tc * TN]);
            *reinterpret_cast<float4*>(&regN[4]) = *reinterpret_cast<const float4*>(&Bs[kk][tc * TN + 4]);
            #pragma unroll
            for (int i = 0; i < TM; i++)
                #pragma unroll
                for (int j = 0; j < TN; j++)
                    acc[i][j] = fmaf(regM[i], regN[j], acc[i][j]);
        }
        __syncthreads();
    }

    const int gcol0 = blockIdx.x * BN + tc * TN;
    #pragma unroll
    for (int i = 0; i < TM; i++) {
        int row = tr * TM + i;
        #pragma unroll
        for (int j = 0; j < TN; j += 4) {
            float4 v;
            float r0 = acc[i][j + 0] + bias[gcol0 + j + 0];
            float r1 = acc[i][j + 1] + bias[gcol0 + j + 1];
            float r2 = acc[i][j + 2] + bias[gcol0 + j + 2];
            float r3 = acc[i][j + 3] + bias[gcol0 + j + 3];
            if (GELU) { r0 = gelu_exact(r0); r1 = gelu_exact(r1); r2 = gelu_exact(r2); r3 = gelu_exact(r3); }
            v.x = r0; v.y = r1; v.z = r2; v.w = r3;
            *reinterpret_cast<float4*>(&Cblk[(size_t)row * N + tc * TN + j]) = v;
        }
    }
}

// ---------------- VQ: argmin over codes, gather z_q, counts, commitment ---------
__global__ void __launch_bounds__(256) vq_kernel(
    const float* __restrict__ z, const float* __restrict__ cb,
    float* __restrict__ zq, float* __restrict__ idx_out_f)
{
    __shared__ float s_z[DD_E];
    __shared__ float s_dist[256];
    __shared__ int   s_idx[256];
    __shared__ float s_red[DPC];

    const int n   = blockIdx.x;
    const int tid = threadIdx.x;

    s_z[tid] = z[(size_t)n * DD_E + tid];
    __syncthreads();

    float commit_local = 0.0f;  // meaningful on tid 0 only

    for (int c = 0; c < NCB; c++) {
        const float* zc = &s_z[c * DPC];
        float zsq = 0.0f;
        #pragma unroll 8
        for (int d = 0; d < DPC; d++) zsq = fmaf(zc[d], zc[d], zsq);

        const float* cbc = cb + (size_t)c * NKC * DPC;
        float best = INFINITY;
        int bestk = 0x7fffffff;
        for (int k = tid; k < NKC; k += 256) {
            const float* e = cbc + (size_t)k * DPC;
            float dot = 0.0f, esq = 0.0f;
            #pragma unroll 8
            for (int d = 0; d < DPC; d++) {
                float ev = e[d];
                dot = fmaf(zc[d], ev, dot);
                esq = fmaf(ev, ev, esq);
            }
            float dist = zsq - 2.0f * dot + esq;
            if (dist < best) { best = dist; bestk = k; }
        }
        s_dist[tid] = best; s_idx[tid] = bestk;
        __syncthreads();
        for (int s = 128; s > 0; s >>= 1) {
            if (tid < s) {
                float d2 = s_dist[tid + s]; int i2 = s_idx[tid + s];
                if (d2 < s_dist[tid] || (d2 == s_dist[tid] && i2 < s_idx[tid])) {
                    s_dist[tid] = d2; s_idx[tid] = i2;
                }
            }
            __syncthreads();
        }
        const int kmin = s_idx[0];
        __syncthreads();

        const float* e = cbc + (size_t)kmin * DPC;
        if (tid < DPC) {
            float ev = e[tid];
            zq[(size_t)n * DD_E + c * DPC + tid] = ev;
            float diff = zc[tid] - ev;
            s_red[tid] = diff * diff;
        }
        __syncthreads();
        if (tid == 0) {
            float s = 0.0f;
            #pragma unroll 8
            for (int d = 0; d < DPC; d++) s += s_red[d];
            commit_local += s;
            atomicAdd(&g_counts[c * NKC + kmin], 1);
            idx_out_f[(size_t)n * NCB + c] = (float)kmin;
        }
        __syncthreads();
    }
    if (tid == 0) atomicAdd(&g_commit_sum, commit_local);
}

// ---------------- finalize: entropy over counts + scalar outputs ----------------
__global__ void __launch_bounds__(256) finalize_kernel(float* __restrict__ out_scalars)
{
    __shared__ float red[256];
    float s = 0.0f;
    for (int i = threadIdx.x; i < NCB * NKC; i += 256) {
        float p = (float)g_counts[i] / (float)N_TOK;
        s += -p * logf(p + 1e-10f);
    }
    red[threadIdx.x] = s;
    __syncthreads();
    for (int st = 128; st > 0; st >>= 1) {
        if (threadIdx.x < st) red[threadIdx.x] += red[threadIdx.x + st];
        __syncthreads();
    }
    if (threadIdx.x == 0) {
        float entropy    = red[0] / (float)NCB;   // mean over codebooks
        float commitment = 0.25f * g_commit_sum / (float)((size_t)N_TOK * DD_E);
        out_scalars[0] = commitment;  // total == commitment
        out_scalars[1] = commitment;
        out_scalars[2] = entropy;
    }
}

// ---------------- launch --------------------------------------------------------
extern "C" void kernel_launch(void* const* d_in, const int* in_sizes, int n_in,
                              void* d_out, int out_size)
{
    const float* x  = (const float*)d_in[0];
    const float* W1 = (const float*)d_in[1];
    const float* b1 = (const float*)d_in[2];
    const float* W2 = (const float*)d_in[3];
    const float* b2 = (const float*)d_in[4];
    const float* cb = (const float*)d_in[5];
    const float* W3 = (const float*)d_in[6];
    const float* b3 = (const float*)d_in[7];
    const float* W4 = (const float*)d_in[8];
    const float* b4 = (const float*)d_in[9];

    float* out = (float*)d_out;
    float* xvq     = out;                                   // [8192, 4096]
    float* idxf    = out + (size_t)N_TOK * DD_O;            // [8192, 4] as float
    float* scalars = idxf + (size_t)N_TOK * NCB;            // total, commitment, entropy

    float *h1, *z, *zq, *h3;
    cudaGetSymbolAddress((void**)&h1, g_h1);
    cudaGetSymbolAddress((void**)&z,  g_z);
    cudaGetSymbolAddress((void**)&zq, g_zq);
    cudaGetSymbolAddress((void**)&h3, g_h3);

    init_kernel<<<(NCB * NKC + 255) / 256, 256>>>();

    dim3 g1(DD_H1 / 128, N_TOK / 128);
    sgemm_kernel<true ><<<g1, 256>>>(N_TOK, DD_H1, DD_IN, x,  W1, b1, h1);

    dim3 g2(DD_E / 128, N_TOK / 128);
    sgemm_kernel<false><<<g2, 256>>>(N_TOK, DD_E, DD_H1, h1, W2, b2, z);

    vq_kernel<<<N_TOK, 256>>>(z, cb, zq, idxf);

    dim3 g3(DD_H3 / 128, N_TOK / 128);
    sgemm_kernel<true ><<<g3, 256>>>(N_TOK, DD_H3, DD_E, zq, W3, b3, h3);

    dim3 g4(DD_O / 128, N_TOK / 128);
    sgemm_kernel<false><<<g4, 256>>>(N_TOK, DD_O, DD_H3, h3, W4, b4, xvq);

    finalize_kernel<<<1, 256>>>(scalars);
}

// round 3
// speedup vs baseline: 1.6781x; 1.6781x over previous
#include <cuda_runtime.h>
#include <math.h>
#include <stdint.h>

// Problem dims (fixed by the dataset)
#define N_TOK 8192      // B*L
#define DD_IN 1152
#define DD_H1 4608      // 4*D_IN
#define DD_E  256
#define NCB   4         // codebooks
#define NKC   2048      // codes per codebook
#define DPC   64        // dims per codebook
#define DD_H3 16384     // 4*H
#define DD_O  4096      // H

// ---------------- scratch (static device globals; no allocation) ----------------
__device__ float g_h1[(size_t)N_TOK * DD_H1];
__device__ float g_z [(size_t)N_TOK * DD_E];
__device__ float g_zq[(size_t)N_TOK * DD_E];
__device__ float g_h3[(size_t)N_TOK * DD_H3];
__device__ float g_w3t[(size_t)DD_H3 * DD_E];   // W3^T  [16384, 256]
__device__ float g_w4t[(size_t)DD_O * DD_H3];   // W4^T  [4096, 16384]
__device__ int   g_counts[NCB * NKC];
__device__ float g_commit_sum;

__device__ __forceinline__ float gelu_exact(float x) {
    return 0.5f * x * (1.0f + erff(x * 0.70710678118654752440f));
}

__device__ __forceinline__ uint32_t smem_u32(const void* p) {
    uint32_t a;
    asm("{ .reg .u64 t; cvta.to.shared.u64 t, %1; cvt.u32.u64 %0, t; }" : "=r"(a) : "l"(p));
    return a;
}
__device__ __forceinline__ void cp_async16(uint32_t saddr, const void* gaddr) {
    asm volatile("cp.async.cg.shared.global [%0], [%1], 16;" :: "r"(saddr), "l"(gaddr) : "memory");
}
__device__ __forceinline__ void cp_commit() {
    asm volatile("cp.async.commit_group;" ::: "memory");
}
__device__ __forceinline__ uint32_t f2tf32(float x) {
    uint32_t r;
    asm("cvt.rna.tf32.f32 %0, %1;" : "=r"(r) : "f"(x));
    return r;
}
__device__ __forceinline__ void mma_tf32(float* c, const uint32_t* a, const uint32_t* b) {
    asm volatile(
        "mma.sync.aligned.m16n8k8.row.col.f32.tf32.tf32.f32 "
        "{%0,%1,%2,%3}, {%4,%5,%6,%7}, {%8,%9}, {%0,%1,%2,%3};"
        : "+f"(c[0]), "+f"(c[1]), "+f"(c[2]), "+f"(c[3])
        : "r"(a[0]), "r"(a[1]), "r"(a[2]), "r"(a[3]), "r"(b[0]), "r"(b[1]));
}

// ---------------- init: zero accumulators (runs every graph replay) -------------
__global__ void init_kernel() {
    int i = blockIdx.x * blockDim.x + threadIdx.x;
    if (i < NCB * NKC) g_counts[i] = 0;
    if (i == 0) g_commit_sum = 0.0f;
}

// ---------------- transpose: out[c][r] = in[r][c]; R,C divisible by 32 ----------
__global__ void __launch_bounds__(256) transpose_kernel(
    const float* __restrict__ in, float* __restrict__ out, int R, int Ccol)
{
    __shared__ float t[32][33];
    int c = blockIdx.x * 32 + threadIdx.x;
    int r = blockIdx.y * 32 + threadIdx.y;
    #pragma unroll
    for (int i = 0; i < 32; i += 8)
        t[threadIdx.y + i][threadIdx.x] = in[(size_t)(r + i) * Ccol + c];
    __syncthreads();
    int c2 = blockIdx.y * 32 + threadIdx.x;
    int r2 = blockIdx.x * 32 + threadIdx.y;
    #pragma unroll
    for (int i = 0; i < 32; i += 8)
        out[(size_t)(r2 + i) * R + c2] = t[threadIdx.x][threadIdx.y + i];
}

// ---------------- tf32 mma.sync GEMM: C[M,N] = A[M,K] @ BT[N,K]^T + bias --------
// CTA 128x128x32, 8 warps (4 m x 2 n), warp tile 32x64, mma m16n8k8.
// Requires M%128==0, N%128==0, K%32==0.
#define MM_BM 128
#define MM_BN 128
#define MM_BK 32
#define MM_PAD 36                                // floats per SMEM row (bank-safe)
#define MM_STAGE_FLTS (2 * 128 * MM_PAD)         // A tile + B tile per stage
#define MM_SMEM (2 * MM_STAGE_FLTS * 4)          // 2 stages, bytes (73728)

template<bool GELU>
__global__ void __launch_bounds__(256) gemm_mma(
    int M, int N, int K,
    const float* __restrict__ A, const float* __restrict__ BT,
    const float* __restrict__ bias, float* __restrict__ C)
{
    extern __shared__ float sm[];
    const uint32_t smb = smem_u32(sm);

    const int tid  = threadIdx.x;
    const int lane = tid & 31, wid = tid >> 5;
    const int wm = (wid & 3) * 32;        // warp row offset in CTA tile
    const int wn = (wid >> 2) * 64;       // warp col offset
    const int r  = lane >> 2;             // groupID
    const int cc = lane & 3;              // threadID_in_group

    const int m0 = blockIdx.x * MM_BM;
    const int n0 = blockIdx.y * MM_BN;
    const int niter = K / MM_BK;

    // async-copy one k-stage (A 128x32 + B 128x32, rows padded to 36 floats)
    auto issue = [&](int kt, int stage) {
        const float* Ak = A  + (size_t)m0 * K + (size_t)kt * MM_BK;
        const float* Bk = BT + (size_t)n0 * K + (size_t)kt * MM_BK;
        uint32_t aS = smb + (uint32_t)stage * MM_STAGE_FLTS * 4;
        uint32_t bS = aS + 128 * MM_PAD * 4;
        #pragma unroll
        for (int i = 0; i < 4; i++) {
            int idx = tid + i * 256, row = idx >> 3, c4 = idx & 7;
            cp_async16(aS + (uint32_t)(row * MM_PAD + c4 * 4) * 4,
                       Ak + (size_t)row * K + c4 * 4);
        }
        #pragma unroll
        for (int i = 0; i < 4; i++) {
            int idx = tid + i * 256, row = idx >> 3, c4 = idx & 7;
            cp_async16(bS + (uint32_t)(row * MM_PAD + c4 * 4) * 4,
                       Bk + (size_t)row * K + c4 * 4);
        }
        cp_commit();
    };

    float acc[2][8][4];
    #pragma unroll
    for (int mt = 0; mt < 2; mt++)
        #pragma unroll
        for (int nt = 0; nt < 8; nt++)
            #pragma unroll
            for (int j = 0; j < 4; j++) acc[mt][nt][j] = 0.0f;

    issue(0, 0);

    for (int kt = 0; kt < niter; kt++) {
        if (kt + 1 < niter) {
            issue(kt + 1, (kt + 1) & 1);
            asm volatile("cp.async.wait_group 1;" ::: "memory");
        } else {
            asm volatile("cp.async.wait_group 0;" ::: "memory");
        }
        __syncthreads();

        const float* aBuf = sm + (size_t)(kt & 1) * MM_STAGE_FLTS;
        const float* bBuf = aBuf + 128 * MM_PAD;

        #pragma unroll
        for (int ks = 0; ks < 4; ks++) {
            const int kb = ks * 8;
            uint32_t af[2][4], bf[8][2];
            #pragma unroll
            for (int mt = 0; mt < 2; mt++) {
                int row = wm + mt * 16 + r;
                af[mt][0] = f2tf32(aBuf[ row      * MM_PAD + kb + cc    ]);
                af[mt][1] = f2tf32(aBuf[(row + 8) * MM_PAD + kb + cc    ]);
                af[mt][2] = f2tf32(aBuf[ row      * MM_PAD + kb + cc + 4]);
                af[mt][3] = f2tf32(aBuf[(row + 8) * MM_PAD + kb + cc + 4]);
            }
            #pragma unroll
            for (int nt = 0; nt < 8; nt++) {
                int n = wn + nt * 8 + r;
                bf[nt][0] = f2tf32(bBuf[n * MM_PAD + kb + cc    ]);
                bf[nt][1] = f2tf32(bBuf[n * MM_PAD + kb + cc + 4]);
            }
            #pragma unroll
            for (int mt = 0; mt < 2; mt++)
                #pragma unroll
                for (int nt = 0; nt < 8; nt++)
                    mma_tf32(acc[mt][nt], af[mt], bf[nt]);
        }
        __syncthreads();
    }

    // epilogue: bias + optional GELU, float2 stores
    #pragma unroll
    for (int mt = 0; mt < 2; mt++) {
        #pragma unroll
        for (int nt = 0; nt < 8; nt++) {
            int row = m0 + wm + mt * 16 + r;
            int col = n0 + wn + nt * 8 + cc * 2;
            float b0 = bias[col], b1 = bias[col + 1];
            float v0 = acc[mt][nt][0] + b0, v1 = acc[mt][nt][1] + b1;
            float v2 = acc[mt][nt][2] + b0, v3 = acc[mt][nt][3] + b1;
            if (GELU) { v0 = gelu_exact(v0); v1 = gelu_exact(v1);
                        v2 = gelu_exact(v2); v3 = gelu_exact(v3); }
            *(float2*)(C + (size_t)row * N + col)       = make_float2(v0, v1);
            *(float2*)(C + (size_t)(row + 8) * N + col) = make_float2(v2, v3);
        }
    }
}

// ---------------- fp32 SGEMM (exact path for GEMM1/GEMM2) -----------------------
template<bool GELU>
__global__ void __launch_bounds__(256) sgemm_kernel(
    int M, int N, int K,
    const float* __restrict__ A, const float* __restrict__ B,
    const float* __restrict__ bias, float* __restrict__ C)
{
    constexpr int BM = 128, BN = 128, BK = 16, TM = 8, TN = 8;
    __shared__ __align__(16) float As[BK][BM];
    __shared__ __align__(16) float Bs[BK][BN];

    const int tid = threadIdx.x;
    const int tr  = tid / (BN / TN);
    const int tc  = tid % (BN / TN);

    const float* Ablk = A + (size_t)blockIdx.y * BM * K;
    const float* Bblk = B + (size_t)blockIdx.x * BN;
    float*       Cblk = C + (size_t)blockIdx.y * BM * N + (size_t)blockIdx.x * BN;

    const int a_row = tid >> 2;
    const int a_k4  = (tid & 3) * 4;
    const int b_k   = tid >> 5;
    const int b_n4  = (tid & 31) * 4;

    float acc[TM][TN] = {};
    float regM[TM], regN[TN];

    for (int k0 = 0; k0 < K; k0 += BK) {
        #pragma unroll
        for (int i = 0; i < 2; i++) {
            int row = a_row + i * 64;
            float4 v = *reinterpret_cast<const float4*>(&Ablk[(size_t)row * K + k0 + a_k4]);
            As[a_k4 + 0][row] = v.x;
            As[a_k4 + 1][row] = v.y;
            As[a_k4 + 2][row] = v.z;
            As[a_k4 + 3][row] = v.w;
        }
        #pragma unroll
        for (int i = 0; i < 2; i++) {
            int kk = b_k + i * 8;
            *reinterpret_cast<float4*>(&Bs[kk][b_n4]) =
                *reinterpret_cast<const float4*>(&Bblk[(size_t)(k0 + kk) * N + b_n4]);
        }
        __syncthreads();

        #pragma unroll
        for (int kk = 0; kk < BK; kk++) {
            *reinterpret_cast<float4*>(&regM[0]) = *reinterpret_cast<const float4*>(&As[kk][tr * TM]);
            *reinterpret_cast<float4*>(&regM[4]) = *reinterpret_cast<const float4*>(&As[kk][tr * TM + 4]);
            *reinterpret_cast<float4*>(&regN[0]) = *reinterpret_cast<const float4*>(&Bs[kk][tc * TN]);
            *reinterpret_cast<float4*>(&regN[4]) = *reinterpret_cast<const float4*>(&Bs[kk][tc * TN + 4]);
            #pragma unroll
            for (int i = 0; i < TM; i++)
                #pragma unroll
                for (int j = 0; j < TN; j++)
                    acc[i][j] = fmaf(regM[i], regN[j], acc[i][j]);
        }
        __syncthreads();
    }

    const int gcol0 = blockIdx.x * BN + tc * TN;
    #pragma unroll
    for (int i = 0; i < TM; i++) {
        int row = tr * TM + i;
        #pragma unroll
        for (int j = 0; j < TN; j += 4) {
            float4 v;
            float r0 = acc[i][j + 0] + bias[gcol0 + j + 0];
            float r1 = acc[i][j + 1] + bias[gcol0 + j + 1];
            float r2 = acc[i][j + 2] + bias[gcol0 + j + 2];
            float r3 = acc[i][j + 3] + bias[gcol0 + j + 3];
            if (GELU) { r0 = gelu_exact(r0); r1 = gelu_exact(r1); r2 = gelu_exact(r2); r3 = gelu_exact(r3); }
            v.x = r0; v.y = r1; v.z = r2; v.w = r3;
            *reinterpret_cast<float4*>(&Cblk[(size_t)row * N + tc * TN + j]) = v;
        }
    }
}

// ---------------- VQ: argmin over codes, gather z_q, counts, commitment ---------
__global__ void __launch_bounds__(256) vq_kernel(
    const float* __restrict__ z, const float* __restrict__ cb,
    float* __restrict__ zq, float* __restrict__ idx_out_f)
{
    __shared__ float s_z[DD_E];
    __shared__ float s_dist[256];
    __shared__ int   s_idx[256];
    __shared__ float s_red[DPC];

    const int n   = blockIdx.x;
    const int tid = threadIdx.x;

    s_z[tid] = z[(size_t)n * DD_E + tid];
    __syncthreads();

    float commit_local = 0.0f;

    for (int c = 0; c < NCB; c++) {
        const float* zc = &s_z[c * DPC];
        float zsq = 0.0f;
        #pragma unroll 8
        for (int d = 0; d < DPC; d++) zsq = fmaf(zc[d], zc[d], zsq);

        const float* cbc = cb + (size_t)c * NKC * DPC;
        float best = INFINITY;
        int bestk = 0x7fffffff;
        for (int k = tid; k < NKC; k += 256) {
            const float* e = cbc + (size_t)k * DPC;
            float dot = 0.0f, esq = 0.0f;
            #pragma unroll 8
            for (int d = 0; d < DPC; d++) {
                float ev = e[d];
                dot = fmaf(zc[d], ev, dot);
                esq = fmaf(ev, ev, esq);
            }
            float dist = zsq - 2.0f * dot + esq;
            if (dist < best) { best = dist; bestk = k; }
        }
        s_dist[tid] = best; s_idx[tid] = bestk;
        __syncthreads();
        for (int s = 128; s > 0; s >>= 1) {
            if (tid < s) {
                float d2 = s_dist[tid + s]; int i2 = s_idx[tid + s];
                if (d2 < s_dist[tid] || (d2 == s_dist[tid] && i2 < s_idx[tid])) {
                    s_dist[tid] = d2; s_idx[tid] = i2;
                }
            }
            __syncthreads();
        }
        const int kmin = s_idx[0];
        __syncthreads();

        const float* e = cbc + (size_t)kmin * DPC;
        if (tid < DPC) {
            float ev = e[tid];
            zq[(size_t)n * DD_E + c * DPC + tid] = ev;
            float diff = zc[tid] - ev;
            s_red[tid] = diff * diff;
        }
        __syncthreads();
        if (tid == 0) {
            float s = 0.0f;
            #pragma unroll 8
            for (int d = 0; d < DPC; d++) s += s_red[d];
            commit_local += s;
            atomicAdd(&g_counts[c * NKC + kmin], 1);
            idx_out_f[(size_t)n * NCB + c] = (float)kmin;
        }
        __syncthreads();
    }
    if (tid == 0) atomicAdd(&g_commit_sum, commit_local);
}

// ---------------- finalize: entropy over counts + scalar outputs ----------------
__global__ void __launch_bounds__(256) finalize_kernel(float* __restrict__ out_scalars)
{
    __shared__ float red[256];
    float s = 0.0f;
    for (int i = threadIdx.x; i < NCB * NKC; i += 256) {
        float p = (float)g_counts[i] / (float)N_TOK;
        s += -p * logf(p + 1e-10f);
    }
    red[threadIdx.x] = s;
    __syncthreads();
    for (int st = 128; st > 0; st >>= 1) {
        if (threadIdx.x < st) red[threadIdx.x] += red[threadIdx.x + st];
        __syncthreads();
    }
    if (threadIdx.x == 0) {
        float entropy    = red[0] / (float)NCB;
        float commitment = 0.25f * g_commit_sum / (float)((size_t)N_TOK * DD_E);
        out_scalars[0] = commitment;
        out_scalars[1] = commitment;
        out_scalars[2] = entropy;
    }
}

// ---------------- launch --------------------------------------------------------
extern "C" void kernel_launch(void* const* d_in, const int* in_sizes, int n_in,
                              void* d_out, int out_size)
{
    const float* x  = (const float*)d_in[0];
    const float* W1 = (const float*)d_in[1];
    const float* b1 = (const float*)d_in[2];
    const float* W2 = (const float*)d_in[3];
    const float* b2 = (const float*)d_in[4];
    const float* cb = (const float*)d_in[5];
    const float* W3 = (const float*)d_in[6];
    const float* b3 = (const float*)d_in[7];
    const float* W4 = (const float*)d_in[8];
    const float* b4 = (const float*)d_in[9];

    float* out = (float*)d_out;
    float* xvq     = out;
    float* idxf    = out + (size_t)N_TOK * DD_O;
    float* scalars = idxf + (size_t)N_TOK * NCB;

    float *h1, *z, *zq, *h3, *w3t, *w4t;
    cudaGetSymbolAddress((void**)&h1,  g_h1);
    cudaGetSymbolAddress((void**)&z,   g_z);
    cudaGetSymbolAddress((void**)&zq,  g_zq);
    cudaGetSymbolAddress((void**)&h3,  g_h3);
    cudaGetSymbolAddress((void**)&w3t, g_w3t);
    cudaGetSymbolAddress((void**)&w4t, g_w4t);

    cudaFuncSetAttribute(gemm_mma<true>,  cudaFuncAttributeMaxDynamicSharedMemorySize, MM_SMEM);
    cudaFuncSetAttribute(gemm_mma<false>, cudaFuncAttributeMaxDynamicSharedMemorySize, MM_SMEM);

    init_kernel<<<(NCB * NKC + 255) / 256, 256>>>();

    // Transpose W3 [256,16384] -> [16384,256]; W4 [16384,4096] -> [4096,16384]
    transpose_kernel<<<dim3(DD_H3 / 32, DD_E / 32),  dim3(32, 8)>>>(W3, w3t, DD_E,  DD_H3);
    transpose_kernel<<<dim3(DD_O / 32,  DD_H3 / 32), dim3(32, 8)>>>(W4, w4t, DD_H3, DD_O);

    dim3 g1(DD_H1 / 128, N_TOK / 128);
    sgemm_kernel<true ><<<g1, 256>>>(N_TOK, DD_H1, DD_IN, x,  W1, b1, h1);

    dim3 g2(DD_E / 128, N_TOK / 128);
    sgemm_kernel<false><<<g2, 256>>>(N_TOK, DD_E, DD_H1, h1, W2, b2, z);

    vq_kernel<<<N_TOK, 256>>>(z, cb, zq, idxf);

    dim3 g3(N_TOK / MM_BM, DD_H3 / MM_BN);
    gemm_mma<true ><<<g3, 256, MM_SMEM>>>(N_TOK, DD_H3, DD_E, zq, w3t, b3, h3);

    dim3 g4(N_TOK / MM_BM, DD_O / MM_BN);
    gemm_mma<false><<<g4, 256, MM_SMEM>>>(N_TOK, DD_O, DD_H3, h3, w4t, b4, xvq);

    finalize_kernel<<<1, 256>>>(scalars);
}

// round 4
// speedup vs baseline: 1.7641x; 1.0512x over previous
#include <cuda_runtime.h>
#include <math.h>
#include <stdint.h>

// Problem dims (fixed by the dataset)
#define N_TOK 8192      // B*L
#define DD_IN 1152
#define DD_H1 4608      // 4*D_IN
#define DD_E  256
#define NCB   4         // codebooks
#define NKC   2048      // codes per codebook
#define DPC   64        // dims per codebook
#define DD_H3 16384     // 4*H
#define DD_O  4096      // H

// ---------------- scratch (static device globals; no allocation) ----------------
__device__ float g_h1[(size_t)N_TOK * DD_H1];
__device__ float g_z [(size_t)N_TOK * DD_E];
__device__ float g_zq[(size_t)N_TOK * DD_E];
__device__ float g_h3[(size_t)N_TOK * DD_H3];
__device__ float g_w3t[(size_t)DD_H3 * DD_E];   // W3^T  [16384, 256]  (tf32-rounded)
__device__ float g_w4t[(size_t)DD_O * DD_H3];   // W4^T  [4096, 16384] (tf32-rounded)
__device__ int   g_counts[NCB * NKC];
__device__ float g_commit_sum;

__device__ __forceinline__ float gelu_exact(float x) {
    return 0.5f * x * (1.0f + erff(x * 0.70710678118654752440f));
}

__device__ __forceinline__ uint32_t smem_u32(const void* p) {
    uint32_t a;
    asm("{ .reg .u64 t; cvta.to.shared.u64 t, %1; cvt.u32.u64 %0, t; }" : "=r"(a) : "l"(p));
    return a;
}
__device__ __forceinline__ void cp_async16(uint32_t saddr, const void* gaddr) {
    asm volatile("cp.async.cg.shared.global [%0], [%1], 16;" :: "r"(saddr), "l"(gaddr) : "memory");
}
__device__ __forceinline__ void cp_commit() {
    asm volatile("cp.async.commit_group;" ::: "memory");
}
__device__ __forceinline__ uint32_t f2tf32(float x) {
    uint32_t r;
    asm("cvt.rna.tf32.f32 %0, %1;" : "=r"(r) : "f"(x));
    return r;
}
__device__ __forceinline__ float round_tf32(float x) { return __uint_as_float(f2tf32(x)); }

__device__ __forceinline__ void mma_tf32(float* c, const uint32_t* a, const uint32_t* b) {
    asm volatile(
        "mma.sync.aligned.m16n8k8.row.col.f32.tf32.tf32.f32 "
        "{%0,%1,%2,%3}, {%4,%5,%6,%7}, {%8,%9}, {%0,%1,%2,%3};"
        : "+f"(c[0]), "+f"(c[1]), "+f"(c[2]), "+f"(c[3])
        : "r"(a[0]), "r"(a[1]), "r"(a[2]), "r"(a[3]), "r"(b[0]), "r"(b[1]));
}

// ---------------- init: zero accumulators (runs every graph replay) -------------
__global__ void init_kernel() {
    int i = blockIdx.x * blockDim.x + threadIdx.x;
    if (i < NCB * NKC) g_counts[i] = 0;
    if (i == 0) g_commit_sum = 0.0f;
}

// ---------------- transpose: out[c][r] = tf32(in[r][c]) -------------------------
__global__ void __launch_bounds__(256) transpose_kernel(
    const float* __restrict__ in, float* __restrict__ out, int R, int Ccol)
{
    __shared__ float t[32][33];
    int c = blockIdx.x * 32 + threadIdx.x;
    int r = blockIdx.y * 32 + threadIdx.y;
    #pragma unroll
    for (int i = 0; i < 32; i += 8)
        t[threadIdx.y + i][threadIdx.x] = in[(size_t)(r + i) * Ccol + c];
    __syncthreads();
    int c2 = blockIdx.y * 32 + threadIdx.x;
    int r2 = blockIdx.x * 32 + threadIdx.y;
    #pragma unroll
    for (int i = 0; i < 32; i += 8)
        out[(size_t)(r2 + i) * R + c2] = round_tf32(t[threadIdx.x][threadIdx.y + i]);
}

// ---------------- tf32 mma.sync GEMM: C[M,N] = A[M,K] @ BT[N,K]^T + bias --------
// CTA 128x128x32, 8 warps (4 m x 2 n), warp tile 32x64, mma m16n8k8.
// Operands in GMEM must already be tf32-rounded. 3-stage cp.async pipeline.
// Grid: blockIdx.x = n-block, blockIdx.y = m-block.
#define MM_BM 128
#define MM_BN 128
#define MM_BK 32
#define MM_PAD 36                                // floats per SMEM row (bank-safe)
#define MM_STAGES 3
#define MM_STAGE_FLTS (2 * 128 * MM_PAD)         // A tile + B tile per stage
#define MM_SMEM (MM_STAGES * MM_STAGE_FLTS * 4)  // bytes = 110592

template<bool GELU, bool ROUND_OUT>
__global__ void __launch_bounds__(256, 2) gemm_mma(
    int M, int N, int K,
    const float* __restrict__ A, const float* __restrict__ BT,
    const float* __restrict__ bias, float* __restrict__ C)
{
    extern __shared__ float sm[];
    const uint32_t smb = smem_u32(sm);

    const int tid  = threadIdx.x;
    const int lane = tid & 31, wid = tid >> 5;
    const int wm = (wid & 3) * 32;        // warp row offset in CTA tile
    const int wn = (wid >> 2) * 64;       // warp col offset
    const int r  = lane >> 2;             // groupID
    const int cc = lane & 3;              // threadID_in_group

    const int m0 = blockIdx.y * MM_BM;
    const int n0 = blockIdx.x * MM_BN;
    const int niter = K / MM_BK;

    auto issue = [&](int kt) {
        const int stage = kt % MM_STAGES;
        const float* Ak = A  + (size_t)m0 * K + (size_t)kt * MM_BK;
        const float* Bk = BT + (size_t)n0 * K + (size_t)kt * MM_BK;
        uint32_t aS = smb + (uint32_t)stage * MM_STAGE_FLTS * 4;
        uint32_t bS = aS + 128 * MM_PAD * 4;
        #pragma unroll
        for (int i = 0; i < 4; i++) {
            int idx = tid + i * 256, row = idx >> 3, c4 = idx & 7;
            cp_async16(aS + (uint32_t)(row * MM_PAD + c4 * 4) * 4,
                       Ak + (size_t)row * K + c4 * 4);
        }
        #pragma unroll
        for (int i = 0; i < 4; i++) {
            int idx = tid + i * 256, row = idx >> 3, c4 = idx & 7;
            cp_async16(bS + (uint32_t)(row * MM_PAD + c4 * 4) * 4,
                       Bk + (size_t)row * K + c4 * 4);
        }
        cp_commit();
    };

    float acc[2][8][4];
    #pragma unroll
    for (int mt = 0; mt < 2; mt++)
        #pragma unroll
        for (int nt = 0; nt < 8; nt++)
            #pragma unroll
            for (int j = 0; j < 4; j++) acc[mt][nt][j] = 0.0f;

    issue(0);
    issue(1);

    for (int kt = 0; kt < niter; kt++) {
        if (kt + 1 < niter) {
            asm volatile("cp.async.wait_group 1;" ::: "memory");
        } else {
            asm volatile("cp.async.wait_group 0;" ::: "memory");
        }
        __syncthreads();
        if (kt + 2 < niter) issue(kt + 2);

        const uint32_t* aBuf = (const uint32_t*)(sm + (size_t)(kt % MM_STAGES) * MM_STAGE_FLTS);
        const uint32_t* bBuf = aBuf + 128 * MM_PAD;

        #pragma unroll
        for (int ks = 0; ks < 4; ks++) {
            const int kb = ks * 8;
            uint32_t af[2][4], bf[8][2];
            #pragma unroll
            for (int mt = 0; mt < 2; mt++) {
                int row = wm + mt * 16 + r;
                af[mt][0] = aBuf[ row      * MM_PAD + kb + cc    ];
                af[mt][1] = aBuf[(row + 8) * MM_PAD + kb + cc    ];
                af[mt][2] = aBuf[ row      * MM_PAD + kb + cc + 4];
                af[mt][3] = aBuf[(row + 8) * MM_PAD + kb + cc + 4];
            }
            #pragma unroll
            for (int nt = 0; nt < 8; nt++) {
                int n = wn + nt * 8 + r;
                bf[nt][0] = bBuf[n * MM_PAD + kb + cc    ];
                bf[nt][1] = bBuf[n * MM_PAD + kb + cc + 4];
            }
            #pragma unroll
            for (int mt = 0; mt < 2; mt++)
                #pragma unroll
                for (int nt = 0; nt < 8; nt++)
                    mma_tf32(acc[mt][nt], af[mt], bf[nt]);
        }
    }

    // epilogue: bias + optional GELU (+ optional tf32 rounding for tf32 consumers)
    #pragma unroll
    for (int mt = 0; mt < 2; mt++) {
        #pragma unroll
        for (int nt = 0; nt < 8; nt++) {
            int row = m0 + wm + mt * 16 + r;
            int col = n0 + wn + nt * 8 + cc * 2;
            float b0 = bias[col], b1 = bias[col + 1];
            float v0 = acc[mt][nt][0] + b0, v1 = acc[mt][nt][1] + b1;
            float v2 = acc[mt][nt][2] + b0, v3 = acc[mt][nt][3] + b1;
            if (GELU) { v0 = gelu_exact(v0); v1 = gelu_exact(v1);
                        v2 = gelu_exact(v2); v3 = gelu_exact(v3); }
            if (ROUND_OUT) { v0 = round_tf32(v0); v1 = round_tf32(v1);
                             v2 = round_tf32(v2); v3 = round_tf32(v3); }
            *(float2*)(C + (size_t)row * N + col)       = make_float2(v0, v1);
            *(float2*)(C + (size_t)(row + 8) * N + col) = make_float2(v2, v3);
        }
    }
}

// ---------------- fp32 SGEMM (exact path for GEMM1/GEMM2) -----------------------
template<bool GELU>
__global__ void __launch_bounds__(256) sgemm_kernel(
    int M, int N, int K,
    const float* __restrict__ A, const float* __restrict__ B,
    const float* __restrict__ bias, float* __restrict__ C)
{
    constexpr int BM = 128, BN = 128, BK = 16, TM = 8, TN = 8;
    __shared__ __align__(16) float As[BK][BM];
    __shared__ __align__(16) float Bs[BK][BN];

    const int tid = threadIdx.x;
    const int tr  = tid / (BN / TN);
    const int tc  = tid % (BN / TN);

    const float* Ablk = A + (size_t)blockIdx.y * BM * K;
    const float* Bblk = B + (size_t)blockIdx.x * BN;
    float*       Cblk = C + (size_t)blockIdx.y * BM * N + (size_t)blockIdx.x * BN;

    const int a_row = tid >> 2;
    const int a_k4  = (tid & 3) * 4;
    const int b_k   = tid >> 5;
    const int b_n4  = (tid & 31) * 4;

    float acc[TM][TN] = {};
    float regM[TM], regN[TN];

    for (int k0 = 0; k0 < K; k0 += BK) {
        #pragma unroll
        for (int i = 0; i < 2; i++) {
            int row = a_row + i * 64;
            float4 v = *reinterpret_cast<const float4*>(&Ablk[(size_t)row * K + k0 + a_k4]);
            As[a_k4 + 0][row] = v.x;
            As[a_k4 + 1][row] = v.y;
            As[a_k4 + 2][row] = v.z;
            As[a_k4 + 3][row] = v.w;
        }
        #pragma unroll
        for (int i = 0; i < 2; i++) {
            int kk = b_k + i * 8;
            *reinterpret_cast<float4*>(&Bs[kk][b_n4]) =
                *reinterpret_cast<const float4*>(&Bblk[(size_t)(k0 + kk) * N + b_n4]);
        }
        __syncthreads();

        #pragma unroll
        for (int kk = 0; kk < BK; kk++) {
            *reinterpret_cast<float4*>(&regM[0]) = *reinterpret_cast<const float4*>(&As[kk][tr * TM]);
            *reinterpret_cast<float4*>(&regM[4]) = *reinterpret_cast<const float4*>(&As[kk][tr * TM + 4]);
            *reinterpret_cast<float4*>(&regN[0]) = *reinterpret_cast<const float4*>(&Bs[kk][tc * TN]);
            *reinterpret_cast<float4*>(&regN[4]) = *reinterpret_cast<const float4*>(&Bs[kk][tc * TN + 4]);
            #pragma unroll
            for (int i = 0; i < TM; i++)
                #pragma unroll
                for (int j = 0; j < TN; j++)
                    acc[i][j] = fmaf(regM[i], regN[j], acc[i][j]);
        }
        __syncthreads();
    }

    const int gcol0 = blockIdx.x * BN + tc * TN;
    #pragma unroll
    for (int i = 0; i < TM; i++) {
        int row = tr * TM + i;
        #pragma unroll
        for (int j = 0; j < TN; j += 4) {
            float4 v;
            float r0 = acc[i][j + 0] + bias[gcol0 + j + 0];
            float r1 = acc[i][j + 1] + bias[gcol0 + j + 1];
            float r2 = acc[i][j + 2] + bias[gcol0 + j + 2];
            float r3 = acc[i][j + 3] + bias[gcol0 + j + 3];
            if (GELU) { r0 = gelu_exact(r0); r1 = gelu_exact(r1); r2 = gelu_exact(r2); r3 = gelu_exact(r3); }
            v.x = r0; v.y = r1; v.z = r2; v.w = r3;
            *reinterpret_cast<float4*>(&Cblk[(size_t)row * N + tc * TN + j]) = v;
        }
    }
}

// ---------------- VQ: argmin over codes, gather z_q, counts, commitment ---------
__global__ void __launch_bounds__(256) vq_kernel(
    const float* __restrict__ z, const float* __restrict__ cb,
    float* __restrict__ zq, float* __restrict__ idx_out_f)
{
    __shared__ float s_z[DD_E];
    __shared__ float s_dist[256];
    __shared__ int   s_idx[256];
    __shared__ float s_red[DPC];

    const int n   = blockIdx.x;
    const int tid = threadIdx.x;

    s_z[tid] = z[(size_t)n * DD_E + tid];
    __syncthreads();

    float commit_local = 0.0f;

    for (int c = 0; c < NCB; c++) {
        const float* zc = &s_z[c * DPC];
        float zsq = 0.0f;
        #pragma unroll 8
        for (int d = 0; d < DPC; d++) zsq = fmaf(zc[d], zc[d], zsq);

        const float* cbc = cb + (size_t)c * NKC * DPC;
        float best = INFINITY;
        int bestk = 0x7fffffff;
        for (int k = tid; k < NKC; k += 256) {
            const float* e = cbc + (size_t)k * DPC;
            float dot = 0.0f, esq = 0.0f;
            #pragma unroll 8
            for (int d = 0; d < DPC; d++) {
                float ev = e[d];
                dot = fmaf(zc[d], ev, dot);
                esq = fmaf(ev, ev, esq);
            }
            float dist = zsq - 2.0f * dot + esq;
            if (dist < best) { best = dist; bestk = k; }
        }
        s_dist[tid] = best; s_idx[tid] = bestk;
        __syncthreads();
        for (int s = 128; s > 0; s >>= 1) {
            if (tid < s) {
                float d2 = s_dist[tid + s]; int i2 = s_idx[tid + s];
                if (d2 < s_dist[tid] || (d2 == s_dist[tid] && i2 < s_idx[tid])) {
                    s_dist[tid] = d2; s_idx[tid] = i2;
                }
            }
            __syncthreads();
        }
        const int kmin = s_idx[0];
        __syncthreads();

        const float* e = cbc + (size_t)kmin * DPC;
        if (tid < DPC) {
            float ev = e[tid];
            // zq feeds only the tf32 GEMM3: store pre-rounded to tf32
            zq[(size_t)n * DD_E + c * DPC + tid] = round_tf32(ev);
            float diff = zc[tid] - ev;
            s_red[tid] = diff * diff;
        }
        __syncthreads();
        if (tid == 0) {
            float s = 0.0f;
            #pragma unroll 8
            for (int d = 0; d < DPC; d++) s += s_red[d];
            commit_local += s;
            atomicAdd(&g_counts[c * NKC + kmin], 1);
            idx_out_f[(size_t)n * NCB + c] = (float)kmin;
        }
        __syncthreads();
    }
    if (tid == 0) atomicAdd(&g_commit_sum, commit_local);
}

// ---------------- finalize: entropy over counts + scalar outputs ----------------
__global__ void __launch_bounds__(256) finalize_kernel(float* __restrict__ out_scalars)
{
    __shared__ float red[256];
    float s = 0.0f;
    for (int i = threadIdx.x; i < NCB * NKC; i += 256) {
        float p = (float)g_counts[i] / (float)N_TOK;
        s += -p * logf(p + 1e-10f);
    }
    red[threadIdx.x] = s;
    __syncthreads();
    for (int st = 128; st > 0; st >>= 1) {
        if (threadIdx.x < st) red[threadIdx.x] += red[threadIdx.x + st];
        __syncthreads();
    }
    if (threadIdx.x == 0) {
        float entropy    = red[0] / (float)NCB;
        float commitment = 0.25f * g_commit_sum / (float)((size_t)N_TOK * DD_E);
        out_scalars[0] = commitment;
        out_scalars[1] = commitment;
        out_scalars[2] = entropy;
    }
}

// ---------------- launch --------------------------------------------------------
extern "C" void kernel_launch(void* const* d_in, const int* in_sizes, int n_in,
                              void* d_out, int out_size)
{
    const float* x  = (const float*)d_in[0];
    const float* W1 = (const float*)d_in[1];
    const float* b1 = (const float*)d_in[2];
    const float* W2 = (const float*)d_in[3];
    const float* b2 = (const float*)d_in[4];
    const float* cb = (const float*)d_in[5];
    const float* W3 = (const float*)d_in[6];
    const float* b3 = (const float*)d_in[7];
    const float* W4 = (const float*)d_in[8];
    const float* b4 = (const float*)d_in[9];

    float* out = (float*)d_out;
    float* xvq     = out;
    float* idxf    = out + (size_t)N_TOK * DD_O;
    float* scalars = idxf + (size_t)N_TOK * NCB;

    float *h1, *z, *zq, *h3, *w3t, *w4t;
    cudaGetSymbolAddress((void**)&h1,  g_h1);
    cudaGetSymbolAddress((void**)&z,   g_z);
    cudaGetSymbolAddress((void**)&zq,  g_zq);
    cudaGetSymbolAddress((void**)&h3,  g_h3);
    cudaGetSymbolAddress((void**)&w3t, g_w3t);
    cudaGetSymbolAddress((void**)&w4t, g_w4t);

    cudaFuncSetAttribute((const void*)gemm_mma<true,  true >, cudaFuncAttributeMaxDynamicSharedMemorySize, MM_SMEM);
    cudaFuncSetAttribute((const void*)gemm_mma<false, false>, cudaFuncAttributeMaxDynamicSharedMemorySize, MM_SMEM);

    init_kernel<<<(NCB * NKC + 255) / 256, 256>>>();

    // Transpose (+tf32 round) W3 [256,16384] -> [16384,256]; W4 [16384,4096] -> [4096,16384]
    transpose_kernel<<<dim3(DD_H3 / 32, DD_E / 32),  dim3(32, 8)>>>(W3, w3t, DD_E,  DD_H3);
    transpose_kernel<<<dim3(DD_O / 32,  DD_H3 / 32), dim3(32, 8)>>>(W4, w4t, DD_H3, DD_O);

    dim3 g1(DD_H1 / 128, N_TOK / 128);
    sgemm_kernel<true ><<<g1, 256>>>(N_TOK, DD_H1, DD_IN, x,  W1, b1, h1);

    dim3 g2(DD_E / 128, N_TOK / 128);
    sgemm_kernel<false><<<g2, 256>>>(N_TOK, DD_E, DD_H1, h1, W2, b2, z);

    vq_kernel<<<N_TOK, 256>>>(z, cb, zq, idxf);

    // h3 is tf32-rounded in GEMM3's epilogue (ROUND_OUT=true); x_vq is exact fp32 out.
    dim3 g3(DD_H3 / MM_BN, N_TOK / MM_BM);
    gemm_mma<true,  true ><<<g3, 256, MM_SMEM>>>(N_TOK, DD_H3, DD_E, zq, w3t, b3, h3);

    dim3 g4(DD_O / MM_BN, N_TOK / MM_BM);
    gemm_mma<false, false><<<g4, 256, MM_SMEM>>>(N_TOK, DD_O, DD_H3, h3, w4t, b4, xvq);

    finalize_kernel<<<1, 256>>>(scalars);
}

// round 8
// speedup vs baseline: 2.0810x; 1.1796x over previous
#include <cuda_runtime.h>
#include <cuda_fp16.h>
#include <math.h>
#include <stdint.h>

// Problem dims (fixed by the dataset)
#define N_TOK 8192      // B*L
#define DD_IN 1152
#define DD_H1 4608      // 4*D_IN
#define DD_E  256
#define NCB   4         // codebooks
#define NKC   2048      // codes per codebook
#define DPC   64        // dims per codebook
#define DD_H3 16384     // 4*H
#define DD_O  4096      // H

// ---------------- scratch (static device globals; no allocation) ----------------
__device__ __align__(16) float  g_h1[(size_t)N_TOK * DD_H1];
__device__ __align__(16) float  g_z [(size_t)N_TOK * DD_E];
__device__ __align__(16) __half g_zq[(size_t)N_TOK * DD_E];
__device__ __align__(16) __half g_h3[(size_t)N_TOK * DD_H3];
__device__ __align__(16) __half g_w3t[(size_t)DD_H3 * DD_E];   // W3^T  [16384, 256]
__device__ __align__(16) __half g_w4t[(size_t)DD_O * DD_H3];   // W4^T  [4096, 16384]
__device__ int   g_counts[NCB * NKC];
__device__ float g_commit_sum;

__device__ __forceinline__ float gelu_exact(float x) {
    return 0.5f * x * (1.0f + erff(x * 0.70710678118654752440f));
}

__device__ __forceinline__ uint32_t smem_u32(const void* p) {
    uint32_t a;
    asm("{ .reg .u64 t; cvta.to.shared.u64 t, %1; cvt.u32.u64 %0, t; }" : "=r"(a) : "l"(p));
    return a;
}
__device__ __forceinline__ void cp_async16(uint32_t saddr, const void* gaddr) {
    asm volatile("cp.async.cg.shared.global [%0], [%1], 16;" :: "r"(saddr), "l"(gaddr) : "memory");
}
__device__ __forceinline__ void cp_commit() {
    asm volatile("cp.async.commit_group;" ::: "memory");
}
__device__ __forceinline__ void ldsm4(uint32_t& r0, uint32_t& r1, uint32_t& r2, uint32_t& r3,
                                      uint32_t addr) {
    asm volatile("ldmatrix.sync.aligned.m8n8.x4.shared.b16 {%0,%1,%2,%3}, [%4];"
                 : "=r"(r0), "=r"(r1), "=r"(r2), "=r"(r3) : "r"(addr));
}
__device__ __forceinline__ void mma_f16(float* c, const uint32_t* a, const uint32_t* b) {
    asm volatile(
        "mma.sync.aligned.m16n8k16.row.col.f32.f16.f16.f32 "
        "{%0,%1,%2,%3}, {%4,%5,%6,%7}, {%8,%9}, {%0,%1,%2,%3};"
        : "+f"(c[0]), "+f"(c[1]), "+f"(c[2]), "+f"(c[3])
        : "r"(a[0]), "r"(a[1]), "r"(a[2]), "r"(a[3]), "r"(b[0]), "r"(b[1]));
}

// ---------------- prep: both weight transposes (fp32->fp16) + zero accumulators -
// 1D grid: blocks [0,4096) -> W3 (256x16384 -> 16384x256),
//          blocks [4096,69632) -> W4 (16384x4096 -> 4096x16384). Block (32,8).
__global__ void __launch_bounds__(256) prep_kernel(
    const float* __restrict__ W3, const float* __restrict__ W4,
    __half* __restrict__ w3t, __half* __restrict__ w4t)
{
    const int bid = blockIdx.x;
    const int tx = threadIdx.x, ty = threadIdx.y;
    int gid = bid * 256 + ty * 32 + tx;
    if (gid < NCB * NKC) g_counts[gid] = 0;
    if (gid == 0) g_commit_sum = 0.0f;

    const float* in; __half* outp; int R, Ccol, bx, by;
    if (bid < 4096) { in = W3; outp = w3t; R = DD_E;  Ccol = DD_H3; bx = bid & 511; by = bid >> 9; }
    else { int b2 = bid - 4096; in = W4; outp = w4t; R = DD_H3; Ccol = DD_O;  bx = b2 & 127; by = b2 >> 7; }

    __shared__ float t[32][33];
    int c = bx * 32 + tx, r = by * 32 + ty;
    #pragma unroll
    for (int i = 0; i < 32; i += 8)
        t[ty + i][tx] = in[(size_t)(r + i) * Ccol + c];
    __syncthreads();
    int c2 = by * 32 + tx, r2 = bx * 32 + ty;
    #pragma unroll
    for (int i = 0; i < 32; i += 8)
        outp[(size_t)(r2 + i) * R + c2] = __float2half(t[tx][ty + i]);
}

// ---------------- fp16 mma.sync GEMM: C[M,N] = A[M,K] @ BT[N,K]^T + bias --------
// CTA 128x128x64, 8 warps (4 m x 2 n), warp tile 32x64, mma m16n8k16, ldmatrix.x4.
// A, BT are __half (row length K). 3-stage cp.async pipeline.
// Grid: blockIdx.x = n-block, blockIdx.y = m-block. M%128==0, N%128==0, K%64==0.
#define MM_BM 128
#define MM_BN 128
#define MM_BK 64
#define MM_PADH 72                                // halfs per SMEM row
#define MM_ROWB (MM_PADH * 2)                     // 144 bytes per row
#define MM_TILEB (128 * MM_ROWB)                  // 18432 bytes per tile
#define MM_STAGEB (2 * MM_TILEB)                  // 36864 bytes per stage
#define MM_STAGES 3
#define MM_SMEM (MM_STAGES * MM_STAGEB)           // 110592 bytes

template<bool GELU, typename TOut>
__global__ void __launch_bounds__(256, 2) gemm_mma(
    int M, int N, int K,
    const __half* __restrict__ A, const __half* __restrict__ BT,
    const float* __restrict__ bias, TOut* __restrict__ C)
{
    extern __shared__ char smraw[];
    const uint32_t smb = smem_u32(smraw);

    const int tid  = threadIdx.x;
    const int lane = tid & 31, wid = tid >> 5;
    const int wm = (wid & 3) * 32;        // warp row offset in CTA tile
    const int wn = (wid >> 2) * 64;       // warp col offset
    const int r  = lane >> 2;             // groupID
    const int cc = lane & 3;              // threadID_in_group

    const int m0 = blockIdx.y * MM_BM;
    const int n0 = blockIdx.x * MM_BN;
    const int niter = K / MM_BK;

    // per-thread ldmatrix addresses (byte offsets within a tile)
    const int aRow0 = wm + (lane & 7) + 8 * ((lane >> 3) & 1);
    const uint32_t aOff0 = (uint32_t)(aRow0 * MM_ROWB + 16 * (lane >> 4));
    const int bRow0 = wn + (lane & 7) + 8 * (lane >> 4);
    const uint32_t bOff0 = (uint32_t)(bRow0 * MM_ROWB + 16 * ((lane >> 3) & 1));

    auto issue = [&](int kt) {
        const int stage = kt % MM_STAGES;
        const __half* Ak = A  + (size_t)m0 * K + (size_t)kt * MM_BK;
        const __half* Bk = BT + (size_t)n0 * K + (size_t)kt * MM_BK;
        uint32_t aS = smb + (uint32_t)stage * MM_STAGEB;
        uint32_t bS = aS + MM_TILEB;
        // A tile: 128 rows x 64 halfs = 128B/row = 8 x 16B chunks -> 1024 chunks
        #pragma unroll
        for (int i = 0; i < 4; i++) {
            int idx = tid + i * 256, row = idx >> 3, c16 = idx & 7;
            cp_async16(aS + (uint32_t)(row * MM_ROWB + c16 * 16),
                       Ak + (size_t)row * K + c16 * 8);
        }
        #pragma unroll
        for (int i = 0; i < 4; i++) {
            int idx = tid + i * 256, row = idx >> 3, c16 = idx & 7;
            cp_async16(bS + (uint32_t)(row * MM_ROWB + c16 * 16),
                       Bk + (size_t)row * K + c16 * 8);
        }
        cp_commit();
    };

    float acc[2][8][4];
    #pragma unroll
    for (int mt = 0; mt < 2; mt++)
        #pragma unroll
        for (int nt = 0; nt < 8; nt++)
            #pragma unroll
            for (int j = 0; j < 4; j++) acc[mt][nt][j] = 0.0f;

    issue(0);
    issue(1);

    for (int kt = 0; kt < niter; kt++) {
        if (kt + 1 < niter) {
            asm volatile("cp.async.wait_group 1;" ::: "memory");
        } else {
            asm volatile("cp.async.wait_group 0;" ::: "memory");
        }
        __syncthreads();
        if (kt + 2 < niter) issue(kt + 2);

        const uint32_t aBase = smb + (uint32_t)(kt % MM_STAGES) * MM_STAGEB;
        const uint32_t bBase = aBase + MM_TILEB;

        #pragma unroll
        for (int ks = 0; ks < 4; ks++) {           // 4 x k16 = BK 64
            const uint32_t kb = (uint32_t)ks * 32; // bytes
            uint32_t af[2][4], bf[8][2];
            #pragma unroll
            for (int mt = 0; mt < 2; mt++)
                ldsm4(af[mt][0], af[mt][1], af[mt][2], af[mt][3],
                      aBase + aOff0 + (uint32_t)mt * (16 * MM_ROWB) + kb);
            #pragma unroll
            for (int p = 0; p < 4; p++)
                ldsm4(bf[2 * p][0], bf[2 * p][1], bf[2 * p + 1][0], bf[2 * p + 1][1],
                      bBase + bOff0 + (uint32_t)p * (16 * MM_ROWB) + kb);
            #pragma unroll
            for (int mt = 0; mt < 2; mt++)
                #pragma unroll
                for (int nt = 0; nt < 8; nt++)
                    mma_f16(acc[mt][nt], af[mt], bf[nt]);
        }
    }

    // epilogue: bias + optional GELU; store float2 or half2
    #pragma unroll
    for (int mt = 0; mt < 2; mt++) {
        #pragma unroll
        for (int nt = 0; nt < 8; nt++) {
            int row = m0 + wm + mt * 16 + r;
            int col = n0 + wn + nt * 8 + cc * 2;
            float b0 = bias[col], b1 = bias[col + 1];
            float v0 = acc[mt][nt][0] + b0, v1 = acc[mt][nt][1] + b1;
            float v2 = acc[mt][nt][2] + b0, v3 = acc[mt][nt][3] + b1;
            if (GELU) { v0 = gelu_exact(v0); v1 = gelu_exact(v1);
                        v2 = gelu_exact(v2); v3 = gelu_exact(v3); }
            if constexpr (sizeof(TOut) == 2) {
                *(__half2*)((__half*)C + (size_t)row * N + col)       = __floats2half2_rn(v0, v1);
                *(__half2*)((__half*)C + (size_t)(row + 8) * N + col) = __floats2half2_rn(v2, v3);
            } else {
                *(float2*)((float*)C + (size_t)row * N + col)       = make_float2(v0, v1);
                *(float2*)((float*)C + (size_t)(row + 8) * N + col) = make_float2(v2, v3);
            }
        }
    }
}

// ---------------- fp32 SGEMM (exact path for GEMM1/GEMM2) -----------------------
template<bool GELU>
__global__ void __launch_bounds__(256) sgemm_kernel(
    int M, int N, int K,
    const float* __restrict__ A, const float* __restrict__ B,
    const float* __restrict__ bias, float* __restrict__ C)
{
    constexpr int BM = 128, BN = 128, BK = 16, TM = 8, TN = 8;
    __shared__ __align__(16) float As[BK][BM];
    __shared__ __align__(16) float Bs[BK][BN];

    const int tid = threadIdx.x;
    const int tr  = tid / (BN / TN);
    const int tc  = tid % (BN / TN);

    const float* Ablk = A + (size_t)blockIdx.y * BM * K;
    const float* Bblk = B + (size_t)blockIdx.x * BN;
    float*       Cblk = C + (size_t)blockIdx.y * BM * N + (size_t)blockIdx.x * BN;

    const int a_row = tid >> 2;
    const int a_k4  = (tid & 3) * 4;
    const int b_k   = tid >> 5;
    const int b_n4  = (tid & 31) * 4;

    float acc[TM][TN] = {};
    float regM[TM], regN[TN];

    for (int k0 = 0; k0 < K; k0 += BK) {
        #pragma unroll
        for (int i = 0; i < 2; i++) {
            int row = a_row + i * 64;
            float4 v = *reinterpret_cast<const float4*>(&Ablk[(size_t)row * K + k0 + a_k4]);
            As[a_k4 + 0][row] = v.x;
            As[a_k4 + 1][row] = v.y;
            As[a_k4 + 2][row] = v.z;
            As[a_k4 + 3][row] = v.w;
        }
        #pragma unroll
        for (int i = 0; i < 2; i++) {
            int kk = b_k + i * 8;
            *reinterpret_cast<float4*>(&Bs[kk][b_n4]) =
                *reinterpret_cast<const float4*>(&Bblk[(size_t)(k0 + kk) * N + b_n4]);
        }
        __syncthreads();

        #pragma unroll
        for (int kk = 0; kk < BK; kk++) {
            *reinterpret_cast<float4*>(&regM[0]) = *reinterpret_cast<const float4*>(&As[kk][tr * TM]);
            *reinterpret_cast<float4*>(&regM[4]) = *reinterpret_cast<const float4*>(&As[kk][tr * TM + 4]);
            *reinterpret_cast<float4*>(&regN[0]) = *reinterpret_cast<const float4*>(&Bs[kk][tc * TN]);
            *reinterpret_cast<float4*>(&regN[4]) = *reinterpret_cast<const float4*>(&Bs[kk][tc * TN + 4]);
            #pragma unroll
            for (int i = 0; i < TM; i++)
                #pragma unroll
                for (int j = 0; j < TN; j++)
                    acc[i][j] = fmaf(regM[i], regN[j], acc[i][j]);
        }
        __syncthreads();
    }

    const int gcol0 = blockIdx.x * BN + tc * TN;
    #pragma unroll
    for (int i = 0; i < TM; i++) {
        int row = tr * TM + i;
        #pragma unroll
        for (int j = 0; j < TN; j += 4) {
            float4 v;
            float r0 = acc[i][j + 0] + bias[gcol0 + j + 0];
            float r1 = acc[i][j + 1] + bias[gcol0 + j + 1];
            float r2 = acc[i][j + 2] + bias[gcol0 + j + 2];
            float r3 = acc[i][j + 3] + bias[gcol0 + j + 3];
            if (GELU) { r0 = gelu_exact(r0); r1 = gelu_exact(r1); r2 = gelu_exact(r2); r3 = gelu_exact(r3); }
            v.x = r0; v.y = r1; v.z = r2; v.w = r3;
            *reinterpret_cast<float4*>(&Cblk[(size_t)row * N + tc * TN + j]) = v;
        }
    }
}

// ---------------- VQ: argmin over codes, gather z_q, counts, commitment ---------
__global__ void __launch_bounds__(256) vq_kernel(
    const float* __restrict__ z, const float* __restrict__ cb,
    __half* __restrict__ zq, float* __restrict__ idx_out_f)
{
    __shared__ float s_z[DD_E];
    __shared__ float s_dist[256];
    __shared__ int   s_idx[256];
    __shared__ float s_red[DPC];

    const int n   = blockIdx.x;
    const int tid = threadIdx.x;

    s_z[tid] = z[(size_t)n * DD_E + tid];
    __syncthreads();

    float commit_local = 0.0f;

    for (int c = 0; c < NCB; c++) {
        const float* zc = &s_z[c * DPC];
        float zsq = 0.0f;
        #pragma unroll 8
        for (int d = 0; d < DPC; d++) zsq = fmaf(zc[d], zc[d], zsq);

        const float* cbc = cb + (size_t)c * NKC * DPC;
        float best = INFINITY;
        int bestk = 0x7fffffff;
        for (int k = tid; k < NKC; k += 256) {
            const float* e = cbc + (size_t)k * DPC;
            float dot = 0.0f, esq = 0.0f;
            #pragma unroll 8
            for (int d = 0; d < DPC; d++) {
                float ev = e[d];
                dot = fmaf(zc[d], ev, dot);
                esq = fmaf(ev, ev, esq);
            }
            float dist = zsq - 2.0f * dot + esq;
            if (dist < best) { best = dist; bestk = k; }
        }
        s_dist[tid] = best; s_idx[tid] = bestk;
        __syncthreads();
        for (int s = 128; s > 0; s >>= 1) {
            if (tid < s) {
                float d2 = s_dist[tid + s]; int i2 = s_idx[tid + s];
                if (d2 < s_dist[tid] || (d2 == s_dist[tid] && i2 < s_idx[tid])) {
                    s_dist[tid] = d2; s_idx[tid] = i2;
                }
            }
            __syncthreads();
        }
        const int kmin = s_idx[0];
        __syncthreads();

        const float* e = cbc + (size_t)kmin * DPC;
        if (tid < DPC) {
            float ev = e[tid];
            zq[(size_t)n * DD_E + c * DPC + tid] = __float2half(ev);  // feeds fp16 GEMM3
            float diff = zc[tid] - ev;
            s_red[tid] = diff * diff;
        }
        __syncthreads();
        if (tid == 0) {
            float s = 0.0f;
            #pragma unroll 8
            for (int d = 0; d < DPC; d++) s += s_red[d];
            commit_local += s;
            atomicAdd(&g_counts[c * NKC + kmin], 1);
            idx_out_f[(size_t)n * NCB + c] = (float)kmin;
        }
        __syncthreads();
    }
    if (tid == 0) atomicAdd(&g_commit_sum, commit_local);
}

// ---------------- finalize: entropy over counts + scalar outputs ----------------
__global__ void __launch_bounds__(256) finalize_kernel(float* __restrict__ out_scalars)
{
    __shared__ float red[256];
    float s = 0.0f;
    for (int i = threadIdx.x; i < NCB * NKC; i += 256) {
        float p = (float)g_counts[i] / (float)N_TOK;
        s += -p * logf(p + 1e-10f);
    }
    red[threadIdx.x] = s;
    __syncthreads();
    for (int st = 128; st > 0; st >>= 1) {
        if (threadIdx.x < st) red[threadIdx.x] += red[threadIdx.x + st];
        __syncthreads();
    }
    if (threadIdx.x == 0) {
        float entropy    = red[0] / (float)NCB;
        float commitment = 0.25f * g_commit_sum / (float)((size_t)N_TOK * DD_E);
        out_scalars[0] = commitment;
        out_scalars[1] = commitment;
        out_scalars[2] = entropy;
    }
}

// ---------------- launch --------------------------------------------------------
extern "C" void kernel_launch(void* const* d_in, const int* in_sizes, int n_in,
                              void* d_out, int out_size)
{
    const float* x  = (const float*)d_in[0];
    const float* W1 = (const float*)d_in[1];
    const float* b1 = (const float*)d_in[2];
    const float* W2 = (const float*)d_in[3];
    const float* b2 = (const float*)d_in[4];
    const float* cb = (const float*)d_in[5];
    const float* W3 = (const float*)d_in[6];
    const float* b3 = (const float*)d_in[7];
    const float* W4 = (const float*)d_in[8];
    const float* b4 = (const float*)d_in[9];

    float* out = (float*)d_out;
    float* xvq     = out;
    float* idxf    = out + (size_t)N_TOK * DD_O;
    float* scalars = idxf + (size_t)N_TOK * NCB;

    float  *h1, *z;
    __half *zq, *h3, *w3t, *w4t;
    cudaGetSymbolAddress((void**)&h1,  g_h1);
    cudaGetSymbolAddress((void**)&z,   g_z);
    cudaGetSymbolAddress((void**)&zq,  g_zq);
    cudaGetSymbolAddress((void**)&h3,  g_h3);
    cudaGetSymbolAddress((void**)&w3t, g_w3t);
    cudaGetSymbolAddress((void**)&w4t, g_w4t);

    cudaFuncSetAttribute((const void*)gemm_mma<true,  __half>, cudaFuncAttributeMaxDynamicSharedMemorySize, MM_SMEM);
    cudaFuncSetAttribute((const void*)gemm_mma<false, float >, cudaFuncAttributeMaxDynamicSharedMemorySize, MM_SMEM);

    // 1: prep (transposes fp32->fp16 + zero accumulators)
    prep_kernel<<<69632, dim3(32, 8)>>>(W3, W4, w3t, w4t);

    // 2-3: exact fp32 GEMMs (feed argmin)
    dim3 g1(DD_H1 / 128, N_TOK / 128);
    sgemm_kernel<true ><<<g1, 256>>>(N_TOK, DD_H1, DD_IN, x,  W1, b1, h1);
    dim3 g2(DD_E / 128, N_TOK / 128);
    sgemm_kernel<false><<<g2, 256>>>(N_TOK, DD_E, DD_H1, h1, W2, b2, z);

    // 4: VQ
    vq_kernel<<<N_TOK, 256>>>(z, cb, zq, idxf);

    // 5-6: fp16 tensor-core GEMMs (x_vq path only)
    dim3 g3(DD_H3 / MM_BN, N_TOK / MM_BM);
    gemm_mma<true,  __half><<<g3, 256, MM_SMEM>>>(N_TOK, DD_H3, DD_E, zq, w3t, b3, h3);

    dim3 g4(DD_O / MM_BN, N_TOK / MM_BM);
    gemm_mma<false, float ><<<g4, 256, MM_SMEM>>>(N_TOK, DD_O, DD_H3, h3, w4t, b4, xvq);

    // 7: scalars
    finalize_kernel<<<1, 256>>>(scalars);
}